// round 16
// baseline (speedup 1.0000x reference)
#include <cuda_runtime.h>
#include <cuda_fp16.h>
#include <cstdint>
#include <math.h>

#define NTOK 98304
#define EXP 6
#define TRAJ_LEN (NTOK*120)
#define SCORE_OFF TRAJ_LEN
#define AUX_OFF   (SCORE_OFF + NTOK)
#define PROBS_OFF (AUX_OFF + 1)
#define NSLOT (2*NTOK)

// ======================= helpers ===========================================
__device__ __forceinline__ uint32_t smem_u32(const void* p) {
    uint32_t a;
    asm("{ .reg .u64 t; cvta.to.shared.u64 t, %1; cvt.u32.u64 %0, t; }" : "=r"(a) : "l"(p));
    return a;
}
__device__ __forceinline__ uint32_t swz(uint32_t o) { return o ^ ((o >> 3) & 0x70); }

__device__ __forceinline__ void ldsm4(uint32_t* r, uint32_t addr) {
    asm volatile("ldmatrix.sync.aligned.m8n8.x4.shared.b16 {%0,%1,%2,%3}, [%4];"
        : "=r"(r[0]), "=r"(r[1]), "=r"(r[2]), "=r"(r[3]) : "r"(addr));
}
__device__ __forceinline__ void mma16816(float* d, const uint32_t* a, const uint32_t* b) {
    asm volatile("mma.sync.aligned.m16n8k16.row.col.f32.f16.f16.f32 "
        "{%0,%1,%2,%3}, {%4,%5,%6,%7}, {%8,%9}, {%0,%1,%2,%3};"
        : "+f"(d[0]), "+f"(d[1]), "+f"(d[2]), "+f"(d[3])
        : "r"(a[0]), "r"(a[1]), "r"(a[2]), "r"(a[3]), "r"(b[0]), "r"(b[1]));
}
#define CP_ASYNC16(dst, src, sz) \
    asm volatile("cp.async.cg.shared.global [%0], [%1], 16, %2;" \
        :: "r"(dst), "l"(src), "r"(sz))
#define CP_COMMIT() asm volatile("cp.async.commit_group;")
#define CP_WAIT0()  asm volatile("cp.async.wait_group 0;")

__device__ __forceinline__ float gelu_exact(float x) {
    return 0.5f * x * (1.0f + erff(x * 0.7071067811865476f));
}
__device__ __forceinline__ uint32_t pack_h2(__half a, __half b) {
    return (uint32_t)__half_as_ushort(a) | ((uint32_t)__half_as_ushort(b) << 16);
}

// ======================= scratch (device globals) ===========================
__device__ __half g_Xh[NTOK*128],  g_Xl[NTOK*128];
__device__ __half g_H1h[NTOK*256], g_H1l[NTOK*256];
__device__ __half g_G1[NSLOT*256];
__device__ __half g_G2[NSLOT*256];
__device__ __half g_S1[NSLOT*128];
__device__ __half g_wr1h[32768],  g_wr1l[32768];
__device__ __half g_wr2h[32768],  g_wr2l[32768];
__device__ __half g_wts1h[294912], g_wts1l[294912];   // merged [tW1|sW1] N=384
__device__ __half g_wt2h[393216], g_wt2l[393216];
__device__ __half g_wt3h[196608], g_wt3l[196608];
__device__ __half g_ws2h[49152],  g_ws2l[49152];
__device__ int   g_list[EXP*NTOK];
__device__ float g_wlist[EXP*NTOK];
__device__ int   g_plist[EXP*NTOK];   // primary slots per expert
__device__ int   g_slist[EXP*NTOK];   // secondary slots per expert
__device__ int   g_cnt[8];
__device__ int   g_pcnt[8];
__device__ int   g_scnt[8];
__device__ float g_partials[256*6];

// ======================= prep + conversions ================================
// split x; zero scores + counters
__global__ void prep_x(const float* __restrict__ x, float* __restrict__ out,
                       __half* __restrict__ x0, __half* __restrict__ x1) {
    long i = (long)blockIdx.x * 256 + threadIdx.x;   // 49152 blocks
    float v = x[i];
    __half h = __float2half_rn(v);
    x0[i] = h;
    x1[i] = __float2half_rn(v - __half2float(h));
    if (i < NTOK) out[SCORE_OFF + i] = 0.f;
    if (i < 8) { g_cnt[i] = 0; g_pcnt[i] = 0; g_scnt[i] = 0; }
}

struct WDesc {
    const float* W; __half *o0, *o1;
    int Nin, nloc, npadI, noff, nblocks; long wstride, ostride;
};
struct WDescs { WDesc d[8]; };
__global__ void convert_all(WDescs ds) {
    const WDesc d = ds.d[blockIdx.y];
    if ((int)blockIdx.x >= d.nblocks) return;
    int e = blockIdx.z;
    int idx = blockIdx.x * 256 + threadIdx.x;
    int ce = d.nloc * 64;
    int c = idx / ce, rem = idx - c * ce;
    int n = rem >> 6, kk = rem & 63;
    float v = (n < d.Nin) ? d.W[(long)e * d.wstride + (long)(c * 64 + kk) * d.Nin + n] : 0.f;
    __half h = __float2half_rn(v);
    int ng = d.noff + n;
    uint32_t bo = (uint32_t)(ng >> 3) * 1024u + (uint32_t)(ng & 7) * 128u + (uint32_t)kk * 2u;
    bo = swz(bo);
    long o = (long)e * d.ostride + (long)c * (d.npadI * 64) + (bo >> 1);
    d.o0[o] = h;
    d.o1[o] = __float2half_rn(v - __half2float(h));
}

// ======================= pipelined mma.sync split-fp16 GEMM =================
// Single-buffered, staged once per 64-k chunk; 2 CTA/SM.
// NTERM=3 (router): {AhBh, AhBl, AlBh}.  NTERM=2 (experts): A fp16 x B 2-split.
// GMODE: 0 = A rows compact (roff+row); 1 = token gather (listsB);
//        2 = slot gather (roff + listsB value).
// grid: x = n-slice, y = 128-row block, z = expert.
// L1M: merged [tW1|sW1] weight image; slice 2 routes to score outputs.
// EPI 0: bias+GELU -> fp16 store (split iff NTERM>=3)   EPI 1: router tail
// EPI 3: traj primary: out[tok] = w*(acc+b) (plain store; covers all tokens)
// EPI 5: traj secondary: out[tok] += w*(acc+b) (plain RMW; launch-serialized)
// EPI 4: score fused dot + atomic
template<int NTILE, int K, int EPI, int GMODE, int NTERM, bool L1M>
__global__ void __launch_bounds__(256, 2)
gemmW(const __half* __restrict__ A0b, const __half* __restrict__ A1b,
      const __half* __restrict__ B0b, const __half* __restrict__ B1b, long bStrideE,
      const float* __restrict__ biasB, long biasStrideE,
      const int* __restrict__ listsB, const int* __restrict__ tokList,
      const float* __restrict__ wlB,
      const int* __restrict__ cntArr, const int* __restrict__ cntRoff, int Mfixed,
      __half* __restrict__ o0, __half* __restrict__ o1, int ldN, int npad4,
      const float* __restrict__ biasSB, long biasStrideEs,
      __half* __restrict__ os0, int ldNs,
      float* __restrict__ outF,
      int* __restrict__ listsOut, float* __restrict__ wlistsOut, int* __restrict__ cntsOut,
      int* __restrict__ plistOut, int* __restrict__ slistOut,
      int* __restrict__ pcntOut, int* __restrict__ scntOut,
      const float* __restrict__ w3B, long w3StrideE,
      const float* __restrict__ b3B, int b3Stride)
{
    constexpr int NA = (NTERM >= 3) ? 2 : 1;
    constexpr int NC = K / 64;
    constexpr int NNT = NTILE / 16;
    constexpr int NG  = NNT / 2;
    constexpr int ABYTES = 16384;
    constexpr int BBYTES = NTILE * 128;
    constexpr int EXTRA  = NA * ABYTES + 2 * BBYTES;
    constexpr int NB4 = NTILE * 8;

    extern __shared__ char smem[];
    const int e = blockIdx.z;
    const int nsl = blockIdx.x;
    const bool head = L1M && (nsl == 2);
    int Mrows = cntArr ? cntArr[e] : Mfixed;
    int rowBase = blockIdx.y << 7;
    if (rowBase >= Mrows) return;
    const int* roffSrc = cntRoff ? cntRoff : cntArr;
    int roff = 0;
    if (roffSrc) for (int i = 0; i < e; i++) roff += roffSrc[i];

    const float* bias;
    __half* w0;
    int ld, colBase;
    if (head) {
        bias = biasSB + (long)e * biasStrideEs;
        w0 = os0; ld = ldNs; colBase = 0;
    } else {
        bias = biasB + (long)e * biasStrideE;
        w0 = o0; ld = ldN; colBase = nsl * NTILE;
    }
    const float* wl = wlB ? (wlB + (long)e * NTOK) : nullptr;
    const int* toks = tokList ? (tokList + (long)e * NTOK) : nullptr;
    const float* w3 = w3B ? (w3B + (long)e * w3StrideE) : nullptr;
    const float* b3 = b3B ? (b3B + (long)e * b3Stride) : nullptr;

    const int t = threadIdx.x, lane = t & 31, w = t >> 5;
    const int wm = w & 3, wn = w >> 2;
    uint32_t sb = smem_u32(smem);
    int*   sgat = (int*)(smem + EXTRA);
    float* sw   = (float*)(smem + EXTRA + 512);
    float* lgsm = (float*)(smem + EXTRA + 512 + 3072);
    int*   bcnt = (int*)(smem + EXTRA + 512 + 3072 + 3072);
    int*   bbase = bcnt + 8;
    int*   pc    = bcnt + 16;
    int*   pbase = bcnt + 24;
    int*   sc    = bcnt + 32;
    int*   sbase = bcnt + 40;

    if (GMODE >= 1 && t < 128) {
        int gr = rowBase + t;
        sgat[t] = (gr < Mrows) ? listsB[(long)e * NTOK + gr] : 0;
    }
    if (EPI == 1) {
        for (int i = t; i < 768; i += 256) { sw[i] = w3[i]; lgsm[i] = 0.f; }
        if (t < 8) { bcnt[t] = 0; pc[t] = 0; sc[t] = 0; }
    }
    if (EPI == 4) { if (t < 64) sw[t] = w3[t]; if (t < 128) lgsm[t] = 0.f; }
    __syncthreads();

    const __half* Asp[2] = {A0b, A1b};
    const uint4* Bsp[2] = {
        (const uint4*)(B0b + (long)e * bStrideE),
        (const uint4*)(B1b + (long)e * bStrideE)};
    const int ny4 = nsl * (NTILE * 8);

    uint32_t aoff[2];
#pragma unroll
    for (int mt = 0; mt < 2; mt++) {
        int r = wm * 32 + mt * 16 + (lane & 15);
        aoff[mt] = (uint32_t)((r >> 3) * 1024 + (r & 7) * 128) + (uint32_t)((lane >> 4) * 16);
    }
    uint32_t boff[NG];
#pragma unroll
    for (int g = 0; g < NG; g++) {
        int r = wn * (NTILE / 2) + g * 16 + ((lane >> 4) & 1) * 8 + (lane & 7);
        boff[g] = (uint32_t)((r >> 3) * 1024 + (r & 7) * 128) + (uint32_t)(((lane >> 3) & 1) * 16);
    }

    auto stage = [&](int c) {
#pragma unroll
        for (int a = 0; a < NA; a++) {
            const __half* Ab = Asp[a];
#pragma unroll
            for (int rep = 0; rep < 4; rep++) {
                int i = t + rep * 256;
                int row = i >> 3, seg = i & 7;
                int gr = rowBase + row;
                int val = (gr < Mrows) ? 16 : 0;
                long ar;
                if (GMODE == 0)      ar = (long)roff + (gr < Mrows ? gr : 0);
                else if (GMODE == 1) ar = (long)sgat[row];
                else                 ar = (long)roff + sgat[row];
                const void* src = Ab + ar * (long)K + c * 64 + seg * 8;
                uint32_t dst = sb + a * ABYTES +
                    swz((uint32_t)((row >> 3) * 1024 + (row & 7) * 128 + seg * 16));
                CP_ASYNC16(dst, src, val);
            }
        }
#pragma unroll
        for (int b = 0; b < 2; b++) {
            const uint4* src0 = Bsp[b] + (long)c * npad4 + ny4;
#pragma unroll
            for (int rep = 0; rep < NB4 / 256; rep++) {
                int i = t + rep * 256;
                CP_ASYNC16(sb + NA * ABYTES + b * BBYTES + (uint32_t)i * 16, src0 + i, 16);
            }
        }
        CP_COMMIT();
    };

    float acc[2][NNT][4];
#pragma unroll
    for (int mt = 0; mt < 2; mt++)
#pragma unroll
        for (int nt = 0; nt < NNT; nt++)
#pragma unroll
            for (int q = 0; q < 4; q++) acc[mt][nt][q] = 0.f;

    stage(0);
    for (int c = 0; c < NC; c++) {
        CP_WAIT0();
        __syncthreads();
#pragma unroll
        for (int ks = 0; ks < 4; ks++) {
            uint32_t af[NA][2][4];
#pragma unroll
            for (int a = 0; a < NA; a++)
#pragma unroll
                for (int mt = 0; mt < 2; mt++)
                    ldsm4(af[a][mt], sb + a * ABYTES + swz(aoff[mt] + (uint32_t)ks * 32));
#pragma unroll
            for (int gp = 0; gp < NG; gp += 2) {
                uint32_t bfr[2][2][4];
#pragma unroll
                for (int b = 0; b < 2; b++)
#pragma unroll
                    for (int gi = 0; gi < 2; gi++) {
                        int g = gp + gi;
                        if (g < NG)
                            ldsm4(bfr[b][gi], sb + NA * ABYTES + b * BBYTES +
                                  swz(boff[g] + (uint32_t)ks * 32));
                    }
#pragma unroll
                for (int tt = 0; tt < NTERM; tt++) {
                    int ai = (NTERM >= 3) ? ((tt == 2) ? 1 : 0) : 0;
                    int bi = (tt == 1) ? 1 : 0;
#pragma unroll
                    for (int gi = 0; gi < 2; gi++) {
                        int g = gp + gi;
                        if (g < NG)
#pragma unroll
                            for (int mt = 0; mt < 2; mt++)
#pragma unroll
                                for (int hn = 0; hn < 2; hn++)
                                    mma16816(acc[mt][g * 2 + hn], af[ai][mt],
                                             &bfr[bi][gi][hn * 2]);
                    }
                }
            }
        }
        __syncthreads();
        if (c + 1 < NC) stage(c + 1);
    }

    // ----------------------- epilogue (from fragments) ---------------------
    const int colW = wn * (NTILE / 2);
#pragma unroll
    for (int mt = 0; mt < 2; mt++) {
#pragma unroll
        for (int h8 = 0; h8 < 2; h8++) {
            int rl = wm * 32 + mt * 16 + (lane >> 2) + h8 * 8;
            int row = rowBase + rl;
            bool act = row < Mrows;
            if (EPI == 0) {
                if (act) {
#pragma unroll
                    for (int nt = 0; nt < NNT; nt++) {
                        int gc = colBase + colW + nt * 8 + (lane & 3) * 2;
                        float v0 = gelu_exact(acc[mt][nt][h8 * 2 + 0] + __ldg(&bias[gc]));
                        float v1 = gelu_exact(acc[mt][nt][h8 * 2 + 1] + __ldg(&bias[gc + 1]));
                        __half b0 = __float2half_rn(v0), b1 = __float2half_rn(v1);
                        long off = (long)(roff + row) * ld + gc;
                        *(uint32_t*)(w0 + off) = pack_h2(b0, b1);
                        if (NTERM >= 3) {
                            __half m0 = __float2half_rn(v0 - __half2float(b0));
                            __half m1 = __float2half_rn(v1 - __half2float(b1));
                            *(uint32_t*)(o1 + off) = pack_h2(m0, m1);
                        }
                    }
                }
            } else if (EPI == 3 || EPI == 5) {
                if (act) {
                    int slot = sgat[rl];
                    int tok = toks[slot];
                    float wgt = wl[slot];
                    float* orow = outF + (long)tok * 120;
#pragma unroll
                    for (int nt = 0; nt < NNT; nt++) {
                        int gc = colBase + colW + nt * 8 + (lane & 3) * 2;
#pragma unroll
                        for (int hh = 0; hh < 2; hh++) {
                            int c2 = gc + hh;
                            if (c2 < 120) {
                                float v = wgt * (acc[mt][nt][h8 * 2 + hh] + __ldg(&bias[c2]));
                                if (EPI == 3) orow[c2] = v;
                                else          orow[c2] += v;
                            }
                        }
                    }
                }
            } else if (EPI == 1) {
                float lr[6] = {0.f, 0.f, 0.f, 0.f, 0.f, 0.f};
#pragma unroll
                for (int nt = 0; nt < NNT; nt++) {
#pragma unroll
                    for (int hh = 0; hh < 2; hh++) {
                        int gc = colW + nt * 8 + (lane & 3) * 2 + hh;
                        float h = gelu_exact(acc[mt][nt][h8 * 2 + hh] + __ldg(&bias[gc]));
#pragma unroll
                        for (int ee = 0; ee < 6; ee++) lr[ee] += h * sw[gc * 6 + ee];
                    }
                }
#pragma unroll
                for (int ee = 0; ee < 6; ee++) {
                    lr[ee] += __shfl_xor_sync(0xffffffffu, lr[ee], 1);
                    lr[ee] += __shfl_xor_sync(0xffffffffu, lr[ee], 2);
                }
                if ((lane & 3) == 0 && act)
#pragma unroll
                    for (int ee = 0; ee < 6; ee++) atomicAdd(&lgsm[rl * 6 + ee], lr[ee]);
            } else if (EPI == 4) {
                float sacc = 0.f;
#pragma unroll
                for (int nt = 0; nt < NNT; nt++) {
#pragma unroll
                    for (int hh = 0; hh < 2; hh++) {
                        int gc = colW + nt * 8 + (lane & 3) * 2 + hh;
                        sacc += gelu_exact(acc[mt][nt][h8 * 2 + hh] + __ldg(&bias[gc])) * sw[gc];
                    }
                }
                sacc += __shfl_xor_sync(0xffffffffu, sacc, 1);
                sacc += __shfl_xor_sync(0xffffffffu, sacc, 2);
                if ((lane & 3) == 0 && act) atomicAdd(&lgsm[rl], sacc);
            }
        }
    }

    if (EPI == 1) {
        __syncthreads();
        int row = rowBase + t;
        bool act = (t < 128) && (row < Mrows);
        int i0 = 0, i1 = 1;
        int pos0 = 0, pos1 = 0, posp = 0, poss = 0;
        float w0g = 0.f, w1g = 0.f;
        float lg[6];
        if (act) {
#pragma unroll
            for (int ee = 0; ee < 6; ee++) lg[ee] = lgsm[t * 6 + ee] + b3[ee];
            float mx = lg[0];
#pragma unroll
            for (int ee = 1; ee < 6; ee++) mx = fmaxf(mx, lg[ee]);
            float p[6], s = 0.f;
#pragma unroll
            for (int ee = 0; ee < 6; ee++) { p[ee] = expf(lg[ee] - mx); s += p[ee]; }
            float inv = 1.f / s;
            float* pr = outF + (long)row * 6;
#pragma unroll
            for (int ee = 0; ee < 6; ee++) pr[ee] = p[ee] * inv;
            i0 = 0;
#pragma unroll
            for (int ee = 1; ee < 6; ee++) if (lg[ee] > lg[i0]) i0 = ee;
            i1 = (i0 == 0) ? 1 : 0;
#pragma unroll
            for (int ee = 0; ee < 6; ee++) if (ee != i0 && lg[ee] > lg[i1]) i1 = ee;
            float rr = expf(lg[i1] - lg[i0]);
            w0g = 1.f / (1.f + rr); w1g = rr * w0g;
            pos0 = atomicAdd(&bcnt[i0], 1);
            pos1 = atomicAdd(&bcnt[i1], 1);
            posp = atomicAdd(&pc[i0], 1);
            poss = atomicAdd(&sc[i1], 1);
        }
        __syncthreads();
        if (t < 6) {
            bbase[t] = atomicAdd(&cntsOut[t], bcnt[t]);
            pbase[t] = atomicAdd(&pcntOut[t], pc[t]);
            sbase[t] = atomicAdd(&scntOut[t], sc[t]);
        }
        __syncthreads();
        if (act) {
            int s0 = bbase[i0] + pos0, s1 = bbase[i1] + pos1;
            listsOut[i0 * NTOK + s0] = row;  wlistsOut[i0 * NTOK + s0] = w0g;
            listsOut[i1 * NTOK + s1] = row;  wlistsOut[i1 * NTOK + s1] = w1g;
            plistOut[i0 * NTOK + pbase[i0] + posp] = s0;
            slistOut[i1 * NTOK + sbase[i1] + poss] = s1;
        }
    }
    if (EPI == 4) {
        __syncthreads();
        int row = rowBase + t;
        if (t < 128 && row < Mrows)
            atomicAdd(&outF[toks[row]], wl[row] * (lgsm[t] + b3[0]));
    }
}

// ---------------- aux loss (deterministic 2-stage tree reduction) ----------
__global__ __launch_bounds__(256) void aux_partial(const float* __restrict__ probs,
                                                   float* __restrict__ partials) {
    __shared__ float s[256][6];
    float acc[6] = {0.f, 0.f, 0.f, 0.f, 0.f, 0.f};
    int base = blockIdx.x * 384;
    for (int it = threadIdx.x; it < 384; it += 256) {
        const float* p = probs + (long)(base + it) * 6;
#pragma unroll
        for (int e = 0; e < 6; e++) acc[e] += p[e];
    }
#pragma unroll
    for (int e = 0; e < 6; e++) s[threadIdx.x][e] = acc[e];
    __syncthreads();
    for (int off = 128; off; off >>= 1) {
        if (threadIdx.x < off)
#pragma unroll
            for (int e = 0; e < 6; e++) s[threadIdx.x][e] += s[threadIdx.x + off][e];
        __syncthreads();
    }
    if (threadIdx.x < 6) partials[blockIdx.x * 6 + threadIdx.x] = s[0][threadIdx.x];
}

__global__ __launch_bounds__(256) void aux_final(const float* __restrict__ partials,
                                                 float* __restrict__ out_aux) {
    __shared__ float s[256][6];
#pragma unroll
    for (int e = 0; e < 6; e++) s[threadIdx.x][e] = partials[threadIdx.x * 6 + e];
    __syncthreads();
    for (int off = 128; off; off >>= 1) {
        if (threadIdx.x < off)
#pragma unroll
            for (int e = 0; e < 6; e++) s[threadIdx.x][e] += s[threadIdx.x + off][e];
        __syncthreads();
    }
    if (threadIdx.x == 0) {
        float aux = 0.f;
#pragma unroll
        for (int e = 0; e < 6; e++) {
            float avg = s[0][e] / (float)NTOK;
            aux += avg * avg;
        }
        out_aux[0] = 6.f * aux;
    }
}

// ---------------------------- host launcher --------------------------------
extern "C" void kernel_launch(void* const* d_in, const int* in_sizes, int n_in,
                              void* d_out, int out_size)
{
    const float* x   = (const float*)d_in[0];
    const float* rW1 = (const float*)d_in[1];  const float* rb1 = (const float*)d_in[2];
    const float* rW2 = (const float*)d_in[3];  const float* rb2 = (const float*)d_in[4];
    const float* rW3 = (const float*)d_in[5];  const float* rb3 = (const float*)d_in[6];
    const float* tW1 = (const float*)d_in[7];  const float* tb1 = (const float*)d_in[8];
    const float* tW2 = (const float*)d_in[9];  const float* tb2 = (const float*)d_in[10];
    const float* tW3 = (const float*)d_in[11]; const float* tb3 = (const float*)d_in[12];
    const float* sW1 = (const float*)d_in[13]; const float* sb1 = (const float*)d_in[14];
    const float* sW2 = (const float*)d_in[15]; const float* sb2 = (const float*)d_in[16];
    const float* sW3 = (const float*)d_in[17]; const float* sb3 = (const float*)d_in[18];
    float* out = (float*)d_out;

    __half *Xh,*Xl,*H1h,*H1l,*G1,*G2,*S1;
    __half *wr1h,*wr1l,*wr2h,*wr2l,*wts1h,*wts1l,*wt2h,*wt2l,*wt3h,*wt3l,*ws2h,*ws2l;
    int *list, *cnt, *plist, *slist, *pcnt, *scnt;
    float *wlist, *partials;
    cudaGetSymbolAddress((void**)&Xh, g_Xh);     cudaGetSymbolAddress((void**)&Xl, g_Xl);
    cudaGetSymbolAddress((void**)&H1h, g_H1h);   cudaGetSymbolAddress((void**)&H1l, g_H1l);
    cudaGetSymbolAddress((void**)&G1, g_G1);
    cudaGetSymbolAddress((void**)&G2, g_G2);
    cudaGetSymbolAddress((void**)&S1, g_S1);
    cudaGetSymbolAddress((void**)&wr1h, g_wr1h); cudaGetSymbolAddress((void**)&wr1l, g_wr1l);
    cudaGetSymbolAddress((void**)&wr2h, g_wr2h); cudaGetSymbolAddress((void**)&wr2l, g_wr2l);
    cudaGetSymbolAddress((void**)&wts1h, g_wts1h); cudaGetSymbolAddress((void**)&wts1l, g_wts1l);
    cudaGetSymbolAddress((void**)&wt2h, g_wt2h); cudaGetSymbolAddress((void**)&wt2l, g_wt2l);
    cudaGetSymbolAddress((void**)&wt3h, g_wt3h); cudaGetSymbolAddress((void**)&wt3l, g_wt3l);
    cudaGetSymbolAddress((void**)&ws2h, g_ws2h); cudaGetSymbolAddress((void**)&ws2l, g_ws2l);
    cudaGetSymbolAddress((void**)&list, g_list); cudaGetSymbolAddress((void**)&wlist, g_wlist);
    cudaGetSymbolAddress((void**)&plist, g_plist); cudaGetSymbolAddress((void**)&slist, g_slist);
    cudaGetSymbolAddress((void**)&cnt, g_cnt);
    cudaGetSymbolAddress((void**)&pcnt, g_pcnt); cudaGetSymbolAddress((void**)&scnt, g_scnt);
    cudaGetSymbolAddress((void**)&partials, g_partials);

    const int S_R    = 2*16384 + 2*16384 + 6848;  // 72384 router (2 CTA/SM)
    const int S_E128 = 16384 + 2*16384 + 6848;    // 56000 experts
    const int S_E64  = 16384 + 2*8192  + 6848;    // 39616 score L2
    cudaFuncSetAttribute(gemmW<128,128,0,0,3,false>, cudaFuncAttributeMaxDynamicSharedMemorySize, S_R);
    cudaFuncSetAttribute(gemmW<128,256,1,0,3,false>, cudaFuncAttributeMaxDynamicSharedMemorySize, S_R);
    cudaFuncSetAttribute(gemmW<128,128,0,1,2,true>,  cudaFuncAttributeMaxDynamicSharedMemorySize, S_E128);
    cudaFuncSetAttribute(gemmW<128,256,0,0,2,false>, cudaFuncAttributeMaxDynamicSharedMemorySize, S_E128);
    cudaFuncSetAttribute(gemmW<128,256,3,2,2,false>, cudaFuncAttributeMaxDynamicSharedMemorySize, S_E128);
    cudaFuncSetAttribute(gemmW<128,256,5,2,2,false>, cudaFuncAttributeMaxDynamicSharedMemorySize, S_E128);
    cudaFuncSetAttribute(gemmW<64,128,4,0,2,false>,  cudaFuncAttributeMaxDynamicSharedMemorySize, S_E64);

    // 1. prep (split x, zero scores+counters) + merged weight conversion
    prep_x<<<NTOK*128/256, 256>>>(x, out, Xh, Xl);
    WDescs ds;
    ds.d[0] = {rW1, wr1h, wr1l, 256, 256, 256, 0, 128, 0, 0};
    ds.d[1] = {rW2, wr2h, wr2l, 128, 128, 128, 0, 128, 0, 0};
    ds.d[2] = {tW1, wts1h, wts1l, 256, 256, 384, 0, 128, 128L*256, 49152};
    ds.d[3] = {sW1, wts1h, wts1l, 128, 128, 384, 256, 64, 128L*128, 49152};
    ds.d[4] = {tW2, wt2h, wt2l, 256, 256, 256, 0, 256, 256L*256, 65536};
    ds.d[5] = {tW3, wt3h, wt3l, 120, 128, 128, 0, 128, 256L*120, 32768};
    ds.d[6] = {sW2, ws2h, ws2l, 64, 64, 64, 0, 32, 128L*64, 8192};
    ds.d[7] = {nullptr, nullptr, nullptr, 0, 1, 1, 0, 0, 0, 0};
    convert_all<<<dim3(256,8,6), 256>>>(ds);

    const int GB = NTOK / 128;  // 768

    // 2. router (3-term fp16 split)
    gemmW<128,128,0,0,3,false><<<dim3(2,GB,1),256,S_R>>>(Xh,Xl,
        wr1h,wr1l, 0, rb1, 0,
        nullptr, nullptr, nullptr, nullptr, nullptr, NTOK,
        H1h,H1l, 256, 2048,
        nullptr, 0, nullptr, 0,
        nullptr, nullptr,nullptr,nullptr, nullptr,nullptr,nullptr,nullptr,
        nullptr,0, nullptr,0);
    gemmW<128,256,1,0,3,false><<<dim3(1,GB,1),256,S_R>>>(H1h,H1l,
        wr2h,wr2l, 0, rb2, 0,
        nullptr, nullptr, nullptr, nullptr, nullptr, NTOK,
        nullptr,nullptr, 128, 1024,
        nullptr, 0, nullptr, 0,
        out + PROBS_OFF, list, wlist, cnt, plist, slist, pcnt, scnt,
        rW3, 0, rb3, 0);

    // 3. merged expert stages (z = expert); A fp16 x B 2-split, 2 terms
    gemmW<128,128,0,1,2,true><<<dim3(3,GB,EXP),256,S_E128>>>(Xh,nullptr,
        wts1h, wts1l, 49152, tb1, 256,
        list, nullptr, nullptr, cnt, nullptr, 0,
        G1,nullptr, 256, 3072,
        sb1, 128, S1, 128,
        nullptr, nullptr,nullptr,nullptr, nullptr,nullptr,nullptr,nullptr,
        nullptr,0, nullptr,0);
    gemmW<128,256,0,0,2,false><<<dim3(2,GB,EXP),256,S_E128>>>(G1,nullptr,
        wt2h, wt2l, 65536, tb2, 256,
        nullptr, nullptr, nullptr, cnt, nullptr, 0,
        G2,nullptr, 256, 2048,
        nullptr, 0, nullptr, 0,
        nullptr, nullptr,nullptr,nullptr, nullptr,nullptr,nullptr,nullptr,
        nullptr,0, nullptr,0);
    // traj L3: primary (plain store; covers every token) then secondary (+=)
    gemmW<128,256,3,2,2,false><<<dim3(1,GB,EXP),256,S_E128>>>(G2,nullptr,
        wt3h, wt3l, 32768, tb3, 120,
        plist, list, wlist, pcnt, cnt, 0,
        nullptr,nullptr, 120, 1024,
        nullptr, 0, nullptr, 0,
        out, nullptr,nullptr,nullptr, nullptr,nullptr,nullptr,nullptr,
        nullptr,0, nullptr,0);
    gemmW<128,256,5,2,2,false><<<dim3(1,GB,EXP),256,S_E128>>>(G2,nullptr,
        wt3h, wt3l, 32768, tb3, 120,
        slist, list, wlist, scnt, cnt, 0,
        nullptr,nullptr, 120, 1024,
        nullptr, 0, nullptr, 0,
        out, nullptr,nullptr,nullptr, nullptr,nullptr,nullptr,nullptr,
        nullptr,0, nullptr,0);
    gemmW<64,128,4,0,2,false><<<dim3(1,GB,EXP),256,S_E64>>>(S1,nullptr,
        ws2h, ws2l, 8192, sb2, 64,
        nullptr, list, wlist, cnt, nullptr, 0,
        nullptr,nullptr, 64, 512,
        nullptr, 0, nullptr, 0,
        out + SCORE_OFF, nullptr,nullptr,nullptr, nullptr,nullptr,nullptr,nullptr,
        sW3, 64, sb3, 1);

    // 4. aux loss from probs
    aux_partial<<<256, 256>>>(out + PROBS_OFF, partials);
    aux_final<<<1, 256>>>(partials, out + AUX_OFF);
}

// round 17
// speedup vs baseline: 1.1331x; 1.1331x over previous
#include <cuda_runtime.h>
#include <cuda_fp16.h>
#include <cstdint>
#include <math.h>

#define NTOK 98304
#define EXP 6
#define TRAJ_LEN (NTOK*120)
#define SCORE_OFF TRAJ_LEN
#define AUX_OFF   (SCORE_OFF + NTOK)
#define PROBS_OFF (AUX_OFF + 1)
#define NSLOT (2*NTOK)

// ======================= helpers ===========================================
__device__ __forceinline__ uint32_t smem_u32(const void* p) {
    uint32_t a;
    asm("{ .reg .u64 t; cvta.to.shared.u64 t, %1; cvt.u32.u64 %0, t; }" : "=r"(a) : "l"(p));
    return a;
}
__device__ __forceinline__ uint32_t swz(uint32_t o) { return o ^ ((o >> 3) & 0x70); }

__device__ __forceinline__ void ldsm4(uint32_t* r, uint32_t addr) {
    asm volatile("ldmatrix.sync.aligned.m8n8.x4.shared.b16 {%0,%1,%2,%3}, [%4];"
        : "=r"(r[0]), "=r"(r[1]), "=r"(r[2]), "=r"(r[3]) : "r"(addr));
}
__device__ __forceinline__ void mma16816(float* d, const uint32_t* a, const uint32_t* b) {
    asm volatile("mma.sync.aligned.m16n8k16.row.col.f32.f16.f16.f32 "
        "{%0,%1,%2,%3}, {%4,%5,%6,%7}, {%8,%9}, {%0,%1,%2,%3};"
        : "+f"(d[0]), "+f"(d[1]), "+f"(d[2]), "+f"(d[3])
        : "r"(a[0]), "r"(a[1]), "r"(a[2]), "r"(a[3]), "r"(b[0]), "r"(b[1]));
}
#define CP_ASYNC16(dst, src, sz) \
    asm volatile("cp.async.cg.shared.global [%0], [%1], 16, %2;" \
        :: "r"(dst), "l"(src), "r"(sz))
#define CP_COMMIT() asm volatile("cp.async.commit_group;")
#define CP_WAIT0()  asm volatile("cp.async.wait_group 0;")

__device__ __forceinline__ float gelu_exact(float x) {
    return 0.5f * x * (1.0f + erff(x * 0.7071067811865476f));
}
__device__ __forceinline__ uint32_t pack_h2(__half a, __half b) {
    return (uint32_t)__half_as_ushort(a) | ((uint32_t)__half_as_ushort(b) << 16);
}

// ======================= scratch (device globals) ===========================
__device__ __half g_Xh[NTOK*128],  g_Xl[NTOK*128];
__device__ __half g_H1h[NTOK*256], g_H1l[NTOK*256];
__device__ __half g_G1[NSLOT*256];
__device__ __half g_G2[NSLOT*256];
__device__ __half g_S1[NSLOT*128];
__device__ __half g_wr1h[32768],  g_wr1l[32768];
__device__ __half g_wr2h[32768],  g_wr2l[32768];
__device__ __half g_wts1h[294912], g_wts1l[294912];   // merged [tW1|sW1] N=384
__device__ __half g_wt2h[393216], g_wt2l[393216];
__device__ __half g_wt3h[196608], g_wt3l[196608];
__device__ __half g_ws2h[49152],  g_ws2l[49152];
__device__ int   g_list[EXP*NTOK];
__device__ float g_wlist[EXP*NTOK];
__device__ int   g_cnt[8];
__device__ float g_partials[256*6];

// ======================= init + conversions ================================
__global__ void init_kernel(float* __restrict__ out) {
    long i = (long)blockIdx.x * blockDim.x + threadIdx.x;   // 11616*256 float4s
    ((float4*)out)[i] = make_float4(0.f, 0.f, 0.f, 0.f);    // traj + scores
    if (blockIdx.x == 0 && threadIdx.x < 8) g_cnt[threadIdx.x] = 0;
}

__global__ void convert_x(const float* __restrict__ x,
                          __half* __restrict__ x0, __half* __restrict__ x1) {
    long i = (long)blockIdx.x * 256 + threadIdx.x;
    float v = x[i];
    __half h = __float2half_rn(v);
    x0[i] = h;
    x1[i] = __float2half_rn(v - __half2float(h));
}

struct WDesc {
    const float* W; __half *o0, *o1;
    int Nin, nloc, npadI, noff, nblocks; long wstride, ostride;
};
struct WDescs { WDesc d[8]; };
__global__ void convert_all(WDescs ds) {
    const WDesc d = ds.d[blockIdx.y];
    if ((int)blockIdx.x >= d.nblocks) return;
    int e = blockIdx.z;
    if (d.wstride == 0 && e > 0) return;   // shared (router) tensors: convert once
    int idx = blockIdx.x * 256 + threadIdx.x;
    int ce = d.nloc * 64;
    int c = idx / ce, rem = idx - c * ce;
    int n = rem >> 6, kk = rem & 63;
    float v = (n < d.Nin) ? d.W[(long)e * d.wstride + (long)(c * 64 + kk) * d.Nin + n] : 0.f;
    __half h = __float2half_rn(v);
    int ng = d.noff + n;
    uint32_t bo = (uint32_t)(ng >> 3) * 1024u + (uint32_t)(ng & 7) * 128u + (uint32_t)kk * 2u;
    bo = swz(bo);
    long o = (long)e * d.ostride + (long)c * (d.npadI * 64) + (bo >> 1);
    d.o0[o] = h;
    d.o1[o] = __float2half_rn(v - __half2float(h));
}

// ======================= pipelined mma.sync split-fp16 GEMM =================
// Single-buffered, staged once per 64-k chunk; 2 CTA/SM.
// NTERM=3 (router): {AhBh, AhBl, AlBh} (err ~2^-22).
// NTERM=2 (experts): A single fp16 x B 2-split (err ~1.4e-4/layer).
// grid: x = n-slice, y = 128-row block, z = expert.
// L1M: merged [tW1|sW1] weight image; slice 2 routes to score outputs.
// EPI 0: bias+GELU -> fp16 store (split iff NTERM>=3)   EPI 1: router tail
// EPI 3: traj atomic scatter (gc<120)       EPI 4: score fused dot + atomic
template<int NTILE, int K, int EPI, bool GATHER, int NTERM, bool L1M>
__global__ void __launch_bounds__(256, 2)
gemmW(const __half* __restrict__ A0b, const __half* __restrict__ A1b,
      const __half* __restrict__ B0b, const __half* __restrict__ B1b, long bStrideE,
      const float* __restrict__ biasB, long biasStrideE,
      const int* __restrict__ listsB, const float* __restrict__ wlB,
      const int* __restrict__ cntArr, int Mfixed,
      __half* __restrict__ o0, __half* __restrict__ o1, int ldN, int npad4,
      const float* __restrict__ biasSB, long biasStrideEs,
      __half* __restrict__ os0, int ldNs,
      float* __restrict__ outF,
      int* __restrict__ listsOut, float* __restrict__ wlistsOut, int* __restrict__ cntsOut,
      const float* __restrict__ w3B, long w3StrideE,
      const float* __restrict__ b3B, int b3Stride)
{
    constexpr int NA = (NTERM >= 3) ? 2 : 1;
    constexpr int NC = K / 64;
    constexpr int NNT = NTILE / 16;
    constexpr int NG  = NNT / 2;
    constexpr int ABYTES = 16384;
    constexpr int BBYTES = NTILE * 128;
    constexpr int EXTRA  = NA * ABYTES + 2 * BBYTES;
    constexpr int NB4 = NTILE * 8;

    extern __shared__ char smem[];
    const int e = blockIdx.z;
    const int nsl = blockIdx.x;
    const bool head = L1M && (nsl == 2);
    int Mrows = cntArr ? cntArr[e] : Mfixed;
    int rowBase = blockIdx.y << 7;
    if (rowBase >= Mrows) return;
    int roff = 0;
    if (cntArr) for (int i = 0; i < e; i++) roff += cntArr[i];

    const float* bias;
    __half* w0;
    int ld, colBase;
    if (head) {
        bias = biasSB + (long)e * biasStrideEs;
        w0 = os0; ld = ldNs; colBase = 0;
    } else {
        bias = biasB + (long)e * biasStrideE;
        w0 = o0; ld = ldN; colBase = nsl * NTILE;
    }
    const int* gather = listsB ? (listsB + (long)e * NTOK) : nullptr;
    const float* wl = wlB ? (wlB + (long)e * NTOK) : nullptr;
    const float* w3 = w3B ? (w3B + (long)e * w3StrideE) : nullptr;
    const float* b3 = b3B ? (b3B + (long)e * b3Stride) : nullptr;

    const int t = threadIdx.x, lane = t & 31, w = t >> 5;
    const int wm = w & 3, wn = w >> 2;
    uint32_t sb = smem_u32(smem);
    int*   sgat = (int*)(smem + EXTRA);
    float* sw   = (float*)(smem + EXTRA + 512);
    float* lgsm = (float*)(smem + EXTRA + 512 + 3072);
    int*   bcnt = (int*)(smem + EXTRA + 512 + 3072 + 3072);
    int*   bbase = bcnt + 8;

    if (GATHER && t < 128) { int gr = rowBase + t; sgat[t] = (gr < Mrows) ? gather[gr] : 0; }
    if (EPI == 1) {
        for (int i = t; i < 768; i += 256) { sw[i] = w3[i]; lgsm[i] = 0.f; }
        if (t < 8) bcnt[t] = 0;
    }
    if (EPI == 4) { if (t < 64) sw[t] = w3[t]; if (t < 128) lgsm[t] = 0.f; }
    __syncthreads();

    const __half* Asp[2] = {A0b, A1b};
    const uint4* Bsp[2] = {
        (const uint4*)(B0b + (long)e * bStrideE),
        (const uint4*)(B1b + (long)e * bStrideE)};
    const int ny4 = nsl * (NTILE * 8);

    uint32_t aoff[2];
#pragma unroll
    for (int mt = 0; mt < 2; mt++) {
        int r = wm * 32 + mt * 16 + (lane & 15);
        aoff[mt] = (uint32_t)((r >> 3) * 1024 + (r & 7) * 128) + (uint32_t)((lane >> 4) * 16);
    }
    uint32_t boff[NG];
#pragma unroll
    for (int g = 0; g < NG; g++) {
        int r = wn * (NTILE / 2) + g * 16 + ((lane >> 4) & 1) * 8 + (lane & 7);
        boff[g] = (uint32_t)((r >> 3) * 1024 + (r & 7) * 128) + (uint32_t)(((lane >> 3) & 1) * 16);
    }

    auto stage = [&](int c) {
#pragma unroll
        for (int a = 0; a < NA; a++) {
            const __half* Ab = Asp[a];
#pragma unroll
            for (int rep = 0; rep < 4; rep++) {
                int i = t + rep * 256;
                int row = i >> 3, seg = i & 7;
                int gr = rowBase + row;
                int val = (gr < Mrows) ? 16 : 0;
                long ar = GATHER ? (long)sgat[row]
                                 : (long)roff + (gr < Mrows ? gr : 0);
                const void* src = Ab + ar * (long)K + c * 64 + seg * 8;
                uint32_t dst = sb + a * ABYTES +
                    swz((uint32_t)((row >> 3) * 1024 + (row & 7) * 128 + seg * 16));
                CP_ASYNC16(dst, src, val);
            }
        }
#pragma unroll
        for (int b = 0; b < 2; b++) {
            const uint4* src0 = Bsp[b] + (long)c * npad4 + ny4;
#pragma unroll
            for (int rep = 0; rep < NB4 / 256; rep++) {
                int i = t + rep * 256;
                CP_ASYNC16(sb + NA * ABYTES + b * BBYTES + (uint32_t)i * 16, src0 + i, 16);
            }
        }
        CP_COMMIT();
    };

    float acc[2][NNT][4];
#pragma unroll
    for (int mt = 0; mt < 2; mt++)
#pragma unroll
        for (int nt = 0; nt < NNT; nt++)
#pragma unroll
            for (int q = 0; q < 4; q++) acc[mt][nt][q] = 0.f;

    stage(0);
    for (int c = 0; c < NC; c++) {
        CP_WAIT0();
        __syncthreads();
#pragma unroll
        for (int ks = 0; ks < 4; ks++) {
            uint32_t af[NA][2][4];
#pragma unroll
            for (int a = 0; a < NA; a++)
#pragma unroll
                for (int mt = 0; mt < 2; mt++)
                    ldsm4(af[a][mt], sb + a * ABYTES + swz(aoff[mt] + (uint32_t)ks * 32));
#pragma unroll
            for (int gp = 0; gp < NG; gp += 2) {
                uint32_t bfr[2][2][4];
#pragma unroll
                for (int b = 0; b < 2; b++)
#pragma unroll
                    for (int gi = 0; gi < 2; gi++) {
                        int g = gp + gi;
                        if (g < NG)
                            ldsm4(bfr[b][gi], sb + NA * ABYTES + b * BBYTES +
                                  swz(boff[g] + (uint32_t)ks * 32));
                    }
#pragma unroll
                for (int tt = 0; tt < NTERM; tt++) {
                    int ai = (NTERM >= 3) ? ((tt == 2) ? 1 : 0) : 0;
                    int bi = (tt == 1) ? 1 : 0;
#pragma unroll
                    for (int gi = 0; gi < 2; gi++) {
                        int g = gp + gi;
                        if (g < NG)
#pragma unroll
                            for (int mt = 0; mt < 2; mt++)
#pragma unroll
                                for (int hn = 0; hn < 2; hn++)
                                    mma16816(acc[mt][g * 2 + hn], af[ai][mt],
                                             &bfr[bi][gi][hn * 2]);
                    }
                }
            }
        }
        __syncthreads();
        if (c + 1 < NC) stage(c + 1);
    }

    // ----------------------- epilogue (from fragments) ---------------------
    const int colW = wn * (NTILE / 2);
#pragma unroll
    for (int mt = 0; mt < 2; mt++) {
#pragma unroll
        for (int h8 = 0; h8 < 2; h8++) {
            int rl = wm * 32 + mt * 16 + (lane >> 2) + h8 * 8;
            int row = rowBase + rl;
            bool act = row < Mrows;
            if (EPI == 0) {
                if (act) {
#pragma unroll
                    for (int nt = 0; nt < NNT; nt++) {
                        int gc = colBase + colW + nt * 8 + (lane & 3) * 2;
                        float v0 = gelu_exact(acc[mt][nt][h8 * 2 + 0] + __ldg(&bias[gc]));
                        float v1 = gelu_exact(acc[mt][nt][h8 * 2 + 1] + __ldg(&bias[gc + 1]));
                        __half b0 = __float2half_rn(v0), b1 = __float2half_rn(v1);
                        long off = (long)(roff + row) * ld + gc;
                        *(uint32_t*)(w0 + off) = pack_h2(b0, b1);
                        if (NTERM >= 3) {
                            __half m0 = __float2half_rn(v0 - __half2float(b0));
                            __half m1 = __float2half_rn(v1 - __half2float(b1));
                            *(uint32_t*)(o1 + off) = pack_h2(m0, m1);
                        }
                    }
                }
            } else if (EPI == 3) {
                if (act) {
                    int tok = gather[row];
                    float wgt = wl[row];
                    float* orow = outF + (long)tok * 120;
#pragma unroll
                    for (int nt = 0; nt < NNT; nt++) {
                        int gc = colBase + colW + nt * 8 + (lane & 3) * 2;
                        if (gc < 120)
                            atomicAdd(&orow[gc], wgt * (acc[mt][nt][h8*2+0] + __ldg(&bias[gc])));
                        if (gc + 1 < 120)
                            atomicAdd(&orow[gc + 1], wgt * (acc[mt][nt][h8*2+1] + __ldg(&bias[gc+1])));
                    }
                }
            } else if (EPI == 1) {
                float lr[6] = {0.f, 0.f, 0.f, 0.f, 0.f, 0.f};
#pragma unroll
                for (int nt = 0; nt < NNT; nt++) {
#pragma unroll
                    for (int hh = 0; hh < 2; hh++) {
                        int gc = colW + nt * 8 + (lane & 3) * 2 + hh;
                        float h = gelu_exact(acc[mt][nt][h8 * 2 + hh] + __ldg(&bias[gc]));
#pragma unroll
                        for (int ee = 0; ee < 6; ee++) lr[ee] += h * sw[gc * 6 + ee];
                    }
                }
#pragma unroll
                for (int ee = 0; ee < 6; ee++) {
                    lr[ee] += __shfl_xor_sync(0xffffffffu, lr[ee], 1);
                    lr[ee] += __shfl_xor_sync(0xffffffffu, lr[ee], 2);
                }
                if ((lane & 3) == 0 && act)
#pragma unroll
                    for (int ee = 0; ee < 6; ee++) atomicAdd(&lgsm[rl * 6 + ee], lr[ee]);
            } else if (EPI == 4) {
                float sacc = 0.f;
#pragma unroll
                for (int nt = 0; nt < NNT; nt++) {
#pragma unroll
                    for (int hh = 0; hh < 2; hh++) {
                        int gc = colW + nt * 8 + (lane & 3) * 2 + hh;
                        sacc += gelu_exact(acc[mt][nt][h8 * 2 + hh] + __ldg(&bias[gc])) * sw[gc];
                    }
                }
                sacc += __shfl_xor_sync(0xffffffffu, sacc, 1);
                sacc += __shfl_xor_sync(0xffffffffu, sacc, 2);
                if ((lane & 3) == 0 && act) atomicAdd(&lgsm[rl], sacc);
            }
        }
    }

    if (EPI == 1) {
        __syncthreads();
        int row = rowBase + t;
        bool act = (t < 128) && (row < Mrows);
        int i0 = 0, i1 = 1, pos0 = 0, pos1 = 0; float w0g = 0.f, w1g = 0.f;
        float lg[6];
        if (act) {
#pragma unroll
            for (int ee = 0; ee < 6; ee++) lg[ee] = lgsm[t * 6 + ee] + b3[ee];
            float mx = lg[0];
#pragma unroll
            for (int ee = 1; ee < 6; ee++) mx = fmaxf(mx, lg[ee]);
            float p[6], s = 0.f;
#pragma unroll
            for (int ee = 0; ee < 6; ee++) { p[ee] = expf(lg[ee] - mx); s += p[ee]; }
            float inv = 1.f / s;
            float* pr = outF + (long)row * 6;
#pragma unroll
            for (int ee = 0; ee < 6; ee++) pr[ee] = p[ee] * inv;
            i0 = 0;
#pragma unroll
            for (int ee = 1; ee < 6; ee++) if (lg[ee] > lg[i0]) i0 = ee;
            i1 = (i0 == 0) ? 1 : 0;
#pragma unroll
            for (int ee = 0; ee < 6; ee++) if (ee != i0 && lg[ee] > lg[i1]) i1 = ee;
            float rr = expf(lg[i1] - lg[i0]);
            w0g = 1.f / (1.f + rr); w1g = rr * w0g;
            pos0 = atomicAdd(&bcnt[i0], 1);
            pos1 = atomicAdd(&bcnt[i1], 1);
        }
        __syncthreads();
        if (t < 6) bbase[t] = atomicAdd(&cntsOut[t], bcnt[t]);
        __syncthreads();
        if (act) {
            int s0 = bbase[i0] + pos0, s1 = bbase[i1] + pos1;
            listsOut[i0 * NTOK + s0] = row;  wlistsOut[i0 * NTOK + s0] = w0g;
            listsOut[i1 * NTOK + s1] = row;  wlistsOut[i1 * NTOK + s1] = w1g;
        }
    }
    if (EPI == 4) {
        __syncthreads();
        int row = rowBase + t;
        if (t < 128 && row < Mrows)
            atomicAdd(&outF[gather[row]], wl[row] * (lgsm[t] + b3[0]));
    }
}

// ---------------- aux loss (deterministic 2-stage tree reduction) ----------
__global__ __launch_bounds__(256) void aux_partial(const float* __restrict__ probs,
                                                   float* __restrict__ partials) {
    __shared__ float s[256][6];
    float acc[6] = {0.f, 0.f, 0.f, 0.f, 0.f, 0.f};
    int base = blockIdx.x * 384;
    for (int it = threadIdx.x; it < 384; it += 256) {
        const float* p = probs + (long)(base + it) * 6;
#pragma unroll
        for (int e = 0; e < 6; e++) acc[e] += p[e];
    }
#pragma unroll
    for (int e = 0; e < 6; e++) s[threadIdx.x][e] = acc[e];
    __syncthreads();
    for (int off = 128; off; off >>= 1) {
        if (threadIdx.x < off)
#pragma unroll
            for (int e = 0; e < 6; e++) s[threadIdx.x][e] += s[threadIdx.x + off][e];
        __syncthreads();
    }
    if (threadIdx.x < 6) partials[blockIdx.x * 6 + threadIdx.x] = s[0][threadIdx.x];
}

__global__ __launch_bounds__(256) void aux_final(const float* __restrict__ partials,
                                                 float* __restrict__ out_aux) {
    __shared__ float s[256][6];
#pragma unroll
    for (int e = 0; e < 6; e++) s[threadIdx.x][e] = partials[threadIdx.x * 6 + e];
    __syncthreads();
    for (int off = 128; off; off >>= 1) {
        if (threadIdx.x < off)
#pragma unroll
            for (int e = 0; e < 6; e++) s[threadIdx.x][e] += s[threadIdx.x + off][e];
        __syncthreads();
    }
    if (threadIdx.x == 0) {
        float aux = 0.f;
#pragma unroll
        for (int e = 0; e < 6; e++) {
            float avg = s[0][e] / (float)NTOK;
            aux += avg * avg;
        }
        out_aux[0] = 6.f * aux;
    }
}

// ---------------------------- host launcher --------------------------------
extern "C" void kernel_launch(void* const* d_in, const int* in_sizes, int n_in,
                              void* d_out, int out_size)
{
    const float* x   = (const float*)d_in[0];
    const float* rW1 = (const float*)d_in[1];  const float* rb1 = (const float*)d_in[2];
    const float* rW2 = (const float*)d_in[3];  const float* rb2 = (const float*)d_in[4];
    const float* rW3 = (const float*)d_in[5];  const float* rb3 = (const float*)d_in[6];
    const float* tW1 = (const float*)d_in[7];  const float* tb1 = (const float*)d_in[8];
    const float* tW2 = (const float*)d_in[9];  const float* tb2 = (const float*)d_in[10];
    const float* tW3 = (const float*)d_in[11]; const float* tb3 = (const float*)d_in[12];
    const float* sW1 = (const float*)d_in[13]; const float* sb1 = (const float*)d_in[14];
    const float* sW2 = (const float*)d_in[15]; const float* sb2 = (const float*)d_in[16];
    const float* sW3 = (const float*)d_in[17]; const float* sb3 = (const float*)d_in[18];
    float* out = (float*)d_out;

    __half *Xh,*Xl,*H1h,*H1l,*G1,*G2,*S1;
    __half *wr1h,*wr1l,*wr2h,*wr2l,*wts1h,*wts1l,*wt2h,*wt2l,*wt3h,*wt3l,*ws2h,*ws2l;
    int *list, *cnt; float *wlist, *partials;
    cudaGetSymbolAddress((void**)&Xh, g_Xh);     cudaGetSymbolAddress((void**)&Xl, g_Xl);
    cudaGetSymbolAddress((void**)&H1h, g_H1h);   cudaGetSymbolAddress((void**)&H1l, g_H1l);
    cudaGetSymbolAddress((void**)&G1, g_G1);
    cudaGetSymbolAddress((void**)&G2, g_G2);
    cudaGetSymbolAddress((void**)&S1, g_S1);
    cudaGetSymbolAddress((void**)&wr1h, g_wr1h); cudaGetSymbolAddress((void**)&wr1l, g_wr1l);
    cudaGetSymbolAddress((void**)&wr2h, g_wr2h); cudaGetSymbolAddress((void**)&wr2l, g_wr2l);
    cudaGetSymbolAddress((void**)&wts1h, g_wts1h); cudaGetSymbolAddress((void**)&wts1l, g_wts1l);
    cudaGetSymbolAddress((void**)&wt2h, g_wt2h); cudaGetSymbolAddress((void**)&wt2l, g_wt2l);
    cudaGetSymbolAddress((void**)&wt3h, g_wt3h); cudaGetSymbolAddress((void**)&wt3l, g_wt3l);
    cudaGetSymbolAddress((void**)&ws2h, g_ws2h); cudaGetSymbolAddress((void**)&ws2l, g_ws2l);
    cudaGetSymbolAddress((void**)&list, g_list); cudaGetSymbolAddress((void**)&wlist, g_wlist);
    cudaGetSymbolAddress((void**)&cnt, g_cnt);
    cudaGetSymbolAddress((void**)&partials, g_partials);

    const int S_R    = 2*16384 + 2*16384 + 6720;  // 72256 router (2 CTA/SM)
    const int S_E128 = 16384 + 2*16384 + 6720;    // 55872 experts
    const int S_E64  = 16384 + 2*8192  + 6720;    // 39488 score L2
    cudaFuncSetAttribute(gemmW<128,128,0,false,3,false>, cudaFuncAttributeMaxDynamicSharedMemorySize, S_R);
    cudaFuncSetAttribute(gemmW<128,256,1,false,3,false>, cudaFuncAttributeMaxDynamicSharedMemorySize, S_R);
    cudaFuncSetAttribute(gemmW<128,128,0,true,2,true>,   cudaFuncAttributeMaxDynamicSharedMemorySize, S_E128);
    cudaFuncSetAttribute(gemmW<128,256,0,false,2,false>, cudaFuncAttributeMaxDynamicSharedMemorySize, S_E128);
    cudaFuncSetAttribute(gemmW<128,256,3,false,2,false>, cudaFuncAttributeMaxDynamicSharedMemorySize, S_E128);
    cudaFuncSetAttribute(gemmW<64,128,4,false,2,false>,  cudaFuncAttributeMaxDynamicSharedMemorySize, S_E64);

    // 1. init + conversions
    init_kernel<<<11616, 256>>>(out);
    convert_x<<<NTOK*128/256, 256>>>(x, Xh, Xl);
    WDescs ds;
    ds.d[0] = {rW1, wr1h, wr1l, 256, 256, 256, 0, 128, 0, 0};
    ds.d[1] = {rW2, wr2h, wr2l, 128, 128, 128, 0, 128, 0, 0};
    ds.d[2] = {tW1, wts1h, wts1l, 256, 256, 384, 0, 128, 128L*256, 49152};
    ds.d[3] = {sW1, wts1h, wts1l, 128, 128, 384, 256, 64, 128L*128, 49152};
    ds.d[4] = {tW2, wt2h, wt2l, 256, 256, 256, 0, 256, 256L*256, 65536};
    ds.d[5] = {tW3, wt3h, wt3l, 120, 128, 128, 0, 128, 256L*120, 32768};
    ds.d[6] = {sW2, ws2h, ws2l, 64, 64, 64, 0, 32, 128L*64, 8192};
    ds.d[7] = {nullptr, nullptr, nullptr, 0, 1, 1, 0, 0, 0, 0};
    convert_all<<<dim3(256,8,6), 256>>>(ds);

    const int GB = NTOK / 128;  // 768

    // 2. router (3-term fp16 split: err ~2^-22, no top-2 flip risk)
    gemmW<128,128,0,false,3,false><<<dim3(2,GB,1),256,S_R>>>(Xh,Xl,
        wr1h,wr1l, 0, rb1, 0,
        nullptr, nullptr, nullptr, NTOK,
        H1h,H1l, 256, 2048,
        nullptr, 0, nullptr, 0,
        nullptr, nullptr,nullptr,nullptr, nullptr,0, nullptr,0);
    gemmW<128,256,1,false,3,false><<<dim3(1,GB,1),256,S_R>>>(H1h,H1l,
        wr2h,wr2l, 0, rb2, 0,
        nullptr, nullptr, nullptr, NTOK,
        nullptr,nullptr, 128, 1024,
        nullptr, 0, nullptr, 0,
        out + PROBS_OFF, list, wlist, cnt, rW3, 0, rb3, 0);

    // 3. merged expert stages (z = expert); A single fp16 x B 2-split, 2 terms
    gemmW<128,128,0,true,2,true><<<dim3(3,GB,EXP),256,S_E128>>>(Xh,nullptr,
        wts1h, wts1l, 49152, tb1, 256,
        list, nullptr, cnt, 0,
        G1,nullptr, 256, 3072,
        sb1, 128, S1, 128,
        nullptr, nullptr,nullptr,nullptr, nullptr,0, nullptr,0);
    gemmW<128,256,0,false,2,false><<<dim3(2,GB,EXP),256,S_E128>>>(G1,nullptr,
        wt2h, wt2l, 65536, tb2, 256,
        nullptr, nullptr, cnt, 0,
        G2,nullptr, 256, 2048,
        nullptr, 0, nullptr, 0,
        nullptr, nullptr,nullptr,nullptr, nullptr,0, nullptr,0);
    gemmW<128,256,3,false,2,false><<<dim3(1,GB,EXP),256,S_E128>>>(G2,nullptr,
        wt3h, wt3l, 32768, tb3, 120,
        list, wlist, cnt, 0,
        nullptr,nullptr, 120, 1024,
        nullptr, 0, nullptr, 0,
        out, nullptr,nullptr,nullptr, nullptr,0, nullptr,0);
    gemmW<64,128,4,false,2,false><<<dim3(1,GB,EXP),256,S_E64>>>(S1,nullptr,
        ws2h, ws2l, 8192, sb2, 64,
        list, wlist, cnt, 0,
        nullptr,nullptr, 64, 512,
        nullptr, 0, nullptr, 0,
        out + SCORE_OFF, nullptr,nullptr,nullptr, sW3, 64, sb3, 1);

    // 4. aux loss from probs
    aux_partial<<<256, 256>>>(out + PROBS_OFF, partials);
    aux_final<<<1, 256>>>(partials, out + AUX_OFF);
}